// round 3
// baseline (speedup 1.0000x reference)
#include <cuda_runtime.h>
#include <math.h>

#define BB 2
#define SS 2048
#define DD 1024
#define HH 16
#define DH 64
#define MM (BB*SS)          // 4096
#define SCALE 0.125f        // dh^-0.5

// ------------------------------ scratch ------------------------------------
__device__ float g_xn[MM*DD];
__device__ float g_q [MM*DD];
__device__ float g_k [MM*DD];
__device__ float g_v [MM*DD];
__device__ float g_pe[SS*DD];
__device__ float g_p [SS*DD];
__device__ float g_head[MM*DD];
__device__ float g_scoreC[(size_t)BB*HH*SS*SS];   // content, then attn probs (in-place)
__device__ float g_scoreP[(size_t)BB*HH*SS*SS];   // raw positional scores

// ------------------------------ LayerNorm ----------------------------------
__global__ void ln_kernel(const float* __restrict__ x,
                          const float* __restrict__ g,
                          const float* __restrict__ b,
                          float* __restrict__ xn) {
    int row = blockIdx.x;
    const float* xr = x + (size_t)row * DD;
    float* outr = xn + (size_t)row * DD;
    int t = threadIdx.x;

    float s = 0.f, s2 = 0.f;
    for (int i = t; i < DD; i += 256) { float v = xr[i]; s += v; s2 += v*v; }

    __shared__ float rs[256], rs2[256];
    rs[t] = s; rs2[t] = s2; __syncthreads();
    for (int off = 128; off > 0; off >>= 1) {
        if (t < off) { rs[t] += rs[t+off]; rs2[t] += rs2[t+off]; }
        __syncthreads();
    }
    float mean = rs[0] * (1.0f/DD);
    float var  = rs2[0] * (1.0f/DD) - mean*mean;
    float inv  = rsqrtf(var + 1e-5f);
    for (int i = t; i < DD; i += 256)
        outr[i] = (xr[i] - mean) * inv * g[i] + b[i];
}

// ------------------------------ sinusoidal PE -------------------------------
__global__ void pe_kernel(float* __restrict__ pe) {
    int idx = blockIdx.x * blockDim.x + threadIdx.x;   // over S * D/2
    if (idx >= SS * (DD/2)) return;
    int s = idx / (DD/2);
    int i = idx % (DD/2);
    double div = exp(-(double)(2*i) * log(10000.0) / (double)DD);
    double ang = (double)s * div;
    pe[(size_t)s*DD + 2*i    ] = (float)sin(ang);
    pe[(size_t)s*DD + 2*i + 1] = (float)cos(ang);
}

// --------------------- SGEMM 128x128x8: C = A*W (+bias) ---------------------
// A: [Mrows,1024] row-major, W: [1024,1024] row-major. grid (N/128, M/128), 256 thr.
__global__ void sgemm128(const float* __restrict__ A, const float* __restrict__ W,
                         const float* __restrict__ bias, float* __restrict__ C) {
    __shared__ float As[8][128];
    __shared__ float Bs[8][128];
    int bx = blockIdx.x, by = blockIdx.y;
    int t = threadIdx.x;
    int tx = t & 15, ty = t >> 4;

    int arow = t >> 1, acol = (t & 1) * 4;
    int wrow = t >> 5, wcol = (t & 31) * 4;

    const float* Aptr = A + (size_t)(by*128 + arow) * 1024 + acol;
    const float* Wptr = W + (size_t)wrow * 1024 + bx*128 + wcol;

    float acc[8][8];
#pragma unroll
    for (int a = 0; a < 8; a++)
#pragma unroll
        for (int b = 0; b < 8; b++) acc[a][b] = 0.f;

    for (int k0 = 0; k0 < 1024; k0 += 8) {
        float4 a4 = *(const float4*)(Aptr + k0);
        As[acol+0][arow] = a4.x; As[acol+1][arow] = a4.y;
        As[acol+2][arow] = a4.z; As[acol+3][arow] = a4.w;
        float4 w4 = *(const float4*)(Wptr + (size_t)k0 * 1024);
        *(float4*)&Bs[wrow][wcol] = w4;
        __syncthreads();
#pragma unroll
        for (int kk = 0; kk < 8; kk++) {
            float ra[8], rb[8];
            *(float4*)&ra[0] = *(const float4*)&As[kk][ty*8];
            *(float4*)&ra[4] = *(const float4*)&As[kk][ty*8+4];
            *(float4*)&rb[0] = *(const float4*)&Bs[kk][tx*8];
            *(float4*)&rb[4] = *(const float4*)&Bs[kk][tx*8+4];
#pragma unroll
            for (int a = 0; a < 8; a++)
#pragma unroll
                for (int b = 0; b < 8; b++) acc[a][b] += ra[a]*rb[b];
        }
        __syncthreads();
    }
#pragma unroll
    for (int a = 0; a < 8; a++) {
        int row = by*128 + ty*8 + a;
        float* Cp = C + (size_t)row * 1024 + bx*128 + tx*8;
        float out[8];
#pragma unroll
        for (int b = 0; b < 8; b++) {
            float bv = bias ? bias[bx*128 + tx*8 + b] : 0.f;
            out[b] = acc[a][b] + bv;
        }
        *(float4*)(Cp)   = *(float4*)&out[0];
        *(float4*)(Cp+4) = *(float4*)&out[4];
    }
}

// ------------- batched score GEMM: out[bh,i,j] = (q_i + bias_h) . key_j -----
// use_p=0: key = k (per-batch);  use_p=1: key = p (shared across batch)
__global__ void score_kernel(const float* __restrict__ q,
                             const float* __restrict__ key,
                             const float* __restrict__ bias,
                             float* __restrict__ out, int use_p) {
    int bh = blockIdx.z;
    int b = bh >> 4, h = bh & 15;
    int i0 = blockIdx.y * 64, j0 = blockIdx.x * 64;

    const float* qbase = q + (size_t)b*SS*DD + h*DH;
    const float* kbase = use_p ? (key + h*DH) : (key + (size_t)b*SS*DD + h*DH);
    const float* ub = bias + h*DH;

    __shared__ float Qs[64][65];
    __shared__ float Ks[64][65];
    int t = threadIdx.x;
    int lr = t >> 4, lc = (t & 15) * 4;
    int tx = t & 15, ty = t >> 4;

#pragma unroll
    for (int s2 = 0; s2 < 4; s2++) {
        int row = lr + 16*s2;
        float4 q4 = *(const float4*)(qbase + (size_t)(i0+row)*DD + lc);
        Qs[row][lc+0] = q4.x + ub[lc+0];
        Qs[row][lc+1] = q4.y + ub[lc+1];
        Qs[row][lc+2] = q4.z + ub[lc+2];
        Qs[row][lc+3] = q4.w + ub[lc+3];
        float4 k4 = *(const float4*)(kbase + (size_t)(j0+row)*DD + lc);
        Ks[row][lc+0] = k4.x; Ks[row][lc+1] = k4.y;
        Ks[row][lc+2] = k4.z; Ks[row][lc+3] = k4.w;
    }
    __syncthreads();

    float acc[4][4];
#pragma unroll
    for (int a = 0; a < 4; a++)
#pragma unroll
        for (int c = 0; c < 4; c++) acc[a][c] = 0.f;

#pragma unroll 8
    for (int d = 0; d < 64; d++) {
        float ra[4], rb[4];
#pragma unroll
        for (int a = 0; a < 4; a++) ra[a] = Qs[ty*4+a][d];
#pragma unroll
        for (int c = 0; c < 4; c++) rb[c] = Ks[tx*4+c][d];
#pragma unroll
        for (int a = 0; a < 4; a++)
#pragma unroll
            for (int c = 0; c < 4; c++) acc[a][c] += ra[a]*rb[c];
    }

    size_t base = (size_t)bh * SS * SS;
#pragma unroll
    for (int a = 0; a < 4; a++) {
        float* op = out + base + (size_t)(i0 + ty*4 + a) * SS + j0 + tx*4;
        float4 st = make_float4(acc[a][0], acc[a][1], acc[a][2], acc[a][3]);
        *(float4*)op = st;
    }
}

// ------------- fused relative shift + softmax (in-place into scoreC) --------
__global__ void softmax_kernel(float* __restrict__ scoreC,
                               const float* __restrict__ scoreP) {
    int i  = blockIdx.x;
    int bh = blockIdx.y;
    size_t baseP = (size_t)bh * SS * SS;
    size_t baseC = baseP + (size_t)i * SS;
    int t = threadIdx.x;

    __shared__ float srow[SS];
    __shared__ float red[256];

    float m = -1e30f;
    for (int j = t; j < SS; j += 256) {
        float c = scoreC[baseC + j];
        float pv;
        if (j <= i)          pv = scoreP[baseP + (size_t)i*SS + (SS - 1 - i + j)];
        else if (j == i + 1) pv = 0.f;
        else                 pv = scoreP[baseP + (size_t)(i+1)*SS + (j - i - 2)];
        float sc = (c + pv) * SCALE;
        srow[j] = sc;
        m = fmaxf(m, sc);
    }
    red[t] = m; __syncthreads();
    for (int off = 128; off > 0; off >>= 1) {
        if (t < off) red[t] = fmaxf(red[t], red[t+off]);
        __syncthreads();
    }
    m = red[0];
    __syncthreads();

    float sum = 0.f;
    for (int j = t; j < SS; j += 256) {
        float e = expf(srow[j] - m);
        srow[j] = e;
        sum += e;
    }
    red[t] = sum; __syncthreads();
    for (int off = 128; off > 0; off >>= 1) {
        if (t < off) red[t] += red[t+off];
        __syncthreads();
    }
    float inv = 1.f / red[0];
    for (int j = t; j < SS; j += 256)
        scoreC[baseC + j] = srow[j] * inv;
}

// ----------------- attn @ V: head[b,i,h,:] = sum_j attn * v ----------------
__global__ void av_kernel(const float* __restrict__ attn,
                          const float* __restrict__ v,
                          float* __restrict__ head) {
    int bh = blockIdx.y;
    int b = bh >> 4, h = bh & 15;
    int i0 = blockIdx.x * 64;

    __shared__ float Ats[64][65];
    __shared__ float Vs[64][65];
    int t = threadIdx.x;
    int lr = t >> 4, lc = (t & 15) * 4;
    int tx = t & 15, ty = t >> 4;

    const float* abase = attn + (size_t)bh * SS * SS;
    const float* vbase = v + (size_t)b*SS*DD + h*DH;

    float acc[4][4];
#pragma unroll
    for (int a = 0; a < 4; a++)
#pragma unroll
        for (int c = 0; c < 4; c++) acc[a][c] = 0.f;

    for (int j0 = 0; j0 < SS; j0 += 64) {
#pragma unroll
        for (int s2 = 0; s2 < 4; s2++) {
            int row = lr + 16*s2;
            float4 a4 = *(const float4*)(abase + (size_t)(i0+row)*SS + j0 + lc);
            Ats[row][lc+0] = a4.x; Ats[row][lc+1] = a4.y;
            Ats[row][lc+2] = a4.z; Ats[row][lc+3] = a4.w;
            float4 v4 = *(const float4*)(vbase + (size_t)(j0+row)*DD + lc);
            Vs[row][lc+0] = v4.x; Vs[row][lc+1] = v4.y;
            Vs[row][lc+2] = v4.z; Vs[row][lc+3] = v4.w;
        }
        __syncthreads();
#pragma unroll 8
        for (int jj = 0; jj < 64; jj++) {
            float ra[4], rv[4];
#pragma unroll
            for (int a = 0; a < 4; a++) ra[a] = Ats[ty*4+a][jj];
#pragma unroll
            for (int c = 0; c < 4; c++) rv[c] = Vs[jj][tx*4+c];
#pragma unroll
            for (int a = 0; a < 4; a++)
#pragma unroll
                for (int c = 0; c < 4; c++) acc[a][c] += ra[a]*rv[c];
        }
        __syncthreads();
    }
#pragma unroll
    for (int a = 0; a < 4; a++) {
        float* hp = head + (size_t)b*SS*DD + (size_t)(i0 + ty*4 + a)*DD + h*DH + tx*4;
        float4 st = make_float4(acc[a][0], acc[a][1], acc[a][2], acc[a][3]);
        *(float4*)hp = st;
    }
}

// ------------------------------ launch -------------------------------------
extern "C" void kernel_launch(void* const* d_in, const int* in_sizes, int n_in,
                              void* d_out, int out_size) {
    const float* x    = (const float*)d_in[0];
    const float* ln_g = (const float*)d_in[1];
    const float* ln_b = (const float*)d_in[2];
    const float* Wq   = (const float*)d_in[3];
    const float* bq   = (const float*)d_in[4];
    const float* Wk   = (const float*)d_in[5];
    const float* bk   = (const float*)d_in[6];
    const float* Wv   = (const float*)d_in[7];
    const float* bv   = (const float*)d_in[8];
    const float* Wp   = (const float*)d_in[9];
    const float* Wo   = (const float*)d_in[10];
    const float* bo   = (const float*)d_in[11];
    const float* u_bias = (const float*)d_in[12];
    const float* v_bias = (const float*)d_in[13];
    float* out = (float*)d_out;

    float *xn, *q, *k, *v, *pe, *p, *head, *scoreC, *scoreP;
    cudaGetSymbolAddress((void**)&xn, g_xn);
    cudaGetSymbolAddress((void**)&q, g_q);
    cudaGetSymbolAddress((void**)&k, g_k);
    cudaGetSymbolAddress((void**)&v, g_v);
    cudaGetSymbolAddress((void**)&pe, g_pe);
    cudaGetSymbolAddress((void**)&p, g_p);
    cudaGetSymbolAddress((void**)&head, g_head);
    cudaGetSymbolAddress((void**)&scoreC, g_scoreC);
    cudaGetSymbolAddress((void**)&scoreP, g_scoreP);

    // 1. LayerNorm
    ln_kernel<<<MM, 256>>>(x, ln_g, ln_b, xn);
    // 2. positional encodings
    pe_kernel<<<(SS*(DD/2) + 255)/256, 256>>>(pe);
    // 3. projections
    sgemm128<<<dim3(8, 32), 256>>>(xn, Wq, bq, q);
    sgemm128<<<dim3(8, 32), 256>>>(xn, Wk, bk, k);
    sgemm128<<<dim3(8, 32), 256>>>(xn, Wv, bv, v);
    sgemm128<<<dim3(8, 16), 256>>>(pe, Wp, nullptr, p);
    // 4. scores
    score_kernel<<<dim3(32, 32, BB*HH), 256>>>(q, k, u_bias, scoreC, 0);
    score_kernel<<<dim3(32, 32, BB*HH), 256>>>(q, p, v_bias, scoreP, 1);
    // 5. relative shift + softmax (in-place)
    softmax_kernel<<<dim3(SS, BB*HH), 256>>>(scoreC, scoreP);
    // 6. attn @ V
    av_kernel<<<dim3(32, BB*HH), 256>>>(scoreC, v, head);
    // 7. output projection
    sgemm128<<<dim3(8, 32), 256>>>(head, Wo, bo, out);
}

// round 4
// speedup vs baseline: 2.1532x; 2.1532x over previous
#include <cuda_runtime.h>
#include <math.h>
#include <stdint.h>

#define BB 2
#define SS 2048
#define DD 1024
#define HH 16
#define DH 64
#define MM (BB*SS)          // 4096
#define SCALE 0.125f        // dh^-0.5

// ------------------------------ scratch ------------------------------------
__device__ float g_xn[MM*DD];
__device__ float g_q [MM*DD];
__device__ float g_k [MM*DD];
__device__ float g_v [MM*DD];
__device__ float g_pe[SS*DD];
__device__ float g_p [SS*DD];
__device__ float g_head[MM*DD];
__device__ float g_wt[5*DD*DD];                   // transposed Wq,Wk,Wv,Wp,Wo
__device__ float g_vt[(size_t)BB*HH*DH*SS];       // per-head transposed V
__device__ float g_scoreC[(size_t)BB*HH*SS*SS];   // content, then attn probs
__device__ float g_scoreP[(size_t)BB*HH*SS*SS];   // raw positional scores

// ------------------------------ helpers ------------------------------------
__device__ __forceinline__ uint32_t f2tf(float f) {
    uint32_t u;
    asm("cvt.rna.tf32.f32 %0, %1;" : "=r"(u) : "f"(f));
    return u;
}

__device__ __forceinline__ void mma8(float* c, const uint32_t* a, const uint32_t* b) {
    asm volatile(
        "mma.sync.aligned.m16n8k8.row.col.f32.tf32.tf32.f32 "
        "{%0,%1,%2,%3}, {%4,%5,%6,%7}, {%8,%9}, {%0,%1,%2,%3};"
        : "+f"(c[0]), "+f"(c[1]), "+f"(c[2]), "+f"(c[3])
        : "r"(a[0]), "r"(a[1]), "r"(a[2]), "r"(a[3]), "r"(b[0]), "r"(b[1]));
}

// --------------------- generic nt tf32 GEMM core ---------------------------
// C[BM,BN] = A[BM,K] * Bt[BN,K]^T (+abias broadcast along rows, +cbias on cols)
// 256 threads = 8 warps; warp tile 64x32.
template<int BM, int BN>
__device__ __forceinline__ void gemm_nt_core(
    const float* __restrict__ A, int lda,
    const float* __restrict__ Bt, int ldb,
    float* __restrict__ C, int ldc,
    int K,
    const float* __restrict__ abias,
    const float* __restrict__ cbias)
{
    constexpr int WNB = BN / 32;               // warps across N
    __shared__ __align__(16) uint32_t As[BM][36];
    __shared__ __align__(16) uint32_t Bs[BN][36];

    const int t = threadIdx.x;
    const int wid = t >> 5, lane = t & 31;
    const int wm = wid / WNB, wn = wid % WNB;
    const int lr = lane >> 2, lc = lane & 3;

    float acc[4][4][4];
#pragma unroll
    for (int mf = 0; mf < 4; mf++)
#pragma unroll
        for (int nf = 0; nf < 4; nf++)
#pragma unroll
            for (int r = 0; r < 4; r++) acc[mf][nf][r] = 0.f;

    const int arow = t >> 3;            // 0..31
    const int ac4  = (t & 7) << 2;      // 0,4,...,28

    for (int k0 = 0; k0 < K; k0 += 32) {
        __syncthreads();
#pragma unroll
        for (int it = 0; it < BM/32; it++) {
            int r = arow + it*32;
            float4 v4 = *(const float4*)(A + (size_t)r*lda + k0 + ac4);
            if (abias) {
                v4.x += abias[k0+ac4+0]; v4.y += abias[k0+ac4+1];
                v4.z += abias[k0+ac4+2]; v4.w += abias[k0+ac4+3];
            }
            uint4 u = make_uint4(f2tf(v4.x), f2tf(v4.y), f2tf(v4.z), f2tf(v4.w));
            *(uint4*)&As[r][ac4] = u;
        }
#pragma unroll
        for (int it = 0; it < BN/32; it++) {
            int r = arow + it*32;
            float4 v4 = *(const float4*)(Bt + (size_t)r*ldb + k0 + ac4);
            uint4 u = make_uint4(f2tf(v4.x), f2tf(v4.y), f2tf(v4.z), f2tf(v4.w));
            *(uint4*)&Bs[r][ac4] = u;
        }
        __syncthreads();

#pragma unroll
        for (int kk = 0; kk < 4; kk++) {
            const int kb = kk * 8;
            uint32_t a[4][4], b[4][2];
#pragma unroll
            for (int mf = 0; mf < 4; mf++) {
                int m = wm*64 + mf*16;
                a[mf][0] = As[m+lr  ][kb+lc  ];
                a[mf][1] = As[m+lr+8][kb+lc  ];
                a[mf][2] = As[m+lr  ][kb+lc+4];
                a[mf][3] = As[m+lr+8][kb+lc+4];
            }
#pragma unroll
            for (int nf = 0; nf < 4; nf++) {
                int n = wn*32 + nf*8;
                b[nf][0] = Bs[n+lr][kb+lc  ];
                b[nf][1] = Bs[n+lr][kb+lc+4];
            }
#pragma unroll
            for (int mf = 0; mf < 4; mf++)
#pragma unroll
                for (int nf = 0; nf < 4; nf++)
                    mma8(acc[mf][nf], a[mf], b[nf]);
        }
    }

    // epilogue
#pragma unroll
    for (int mf = 0; mf < 4; mf++) {
        int m = wm*64 + mf*16;
#pragma unroll
        for (int nf = 0; nf < 4; nf++) {
            int n = wn*32 + nf*8 + 2*lc;
            float b0 = cbias ? cbias[n]   : 0.f;
            float b1 = cbias ? cbias[n+1] : 0.f;
            *(float2*)(C + (size_t)(m+lr  )*ldc + n) =
                make_float2(acc[mf][nf][0] + b0, acc[mf][nf][1] + b1);
            *(float2*)(C + (size_t)(m+lr+8)*ldc + n) =
                make_float2(acc[mf][nf][2] + b0, acc[mf][nf][3] + b1);
        }
    }
}

// ------------------------------ wrappers -----------------------------------
// projections: C[M,1024] = A[M,1024] * Wt[1024,1024]^T (+bias)
__global__ void __launch_bounds__(256) proj_tc(
    const float* __restrict__ A, const float* __restrict__ Bt,
    const float* __restrict__ cbias, float* __restrict__ C)
{
    const float* Ab  = A  + (size_t)blockIdx.y * 128 * DD;
    const float* Btb = Bt + (size_t)blockIdx.x * 128 * DD;
    float* Cb = C + (size_t)blockIdx.y * 128 * DD + blockIdx.x * 128;
    gemm_nt_core<128,128>(Ab, DD, Btb, DD, Cb, DD, DD, nullptr,
                          cbias ? cbias + blockIdx.x*128 : nullptr);
}

// scores: out[bh,i,j] = (q_i + bias_h) . key_j ; key_bstride = SS*DD for k, 0 for p
__global__ void __launch_bounds__(256) score_tc(
    const float* __restrict__ q, const float* __restrict__ key,
    const float* __restrict__ bias, float* __restrict__ out, int key_bstride)
{
    int z = blockIdx.z, b = z >> 4, h = z & 15;
    const float* Ab  = q + (size_t)b*SS*DD + h*DH + (size_t)blockIdx.y * 128 * DD;
    const float* Btb = key + (size_t)b*key_bstride + h*DH + (size_t)blockIdx.x * 128 * DD;
    float* Cb = out + (size_t)z*SS*SS + (size_t)blockIdx.y * 128 * SS + blockIdx.x * 128;
    gemm_nt_core<128,128>(Ab, DD, Btb, DD, Cb, SS, DH, bias + h*DH, nullptr);
}

// attn @ V: head[b,i,h,:] = sum_j attn[bh,i,j] * v[b,j,h,:]  (vt = per-head V^T)
__global__ void __launch_bounds__(256) av_tc(
    const float* __restrict__ attn, const float* __restrict__ vt,
    float* __restrict__ head)
{
    int z = blockIdx.z, b = z >> 4, h = z & 15;
    const float* Ab  = attn + (size_t)z*SS*SS + (size_t)blockIdx.x * 256 * SS;
    const float* Btb = vt + (size_t)z*DH*SS;
    float* Cb = head + (size_t)b*SS*DD + (size_t)blockIdx.x * 256 * DD + h*DH;
    gemm_nt_core<256,64>(Ab, SS, Btb, SS, Cb, DD, SS, nullptr, nullptr);
}

// ------------------------------ transposes ---------------------------------
__global__ void transpose1024(const float* __restrict__ src, float* __restrict__ dst) {
    __shared__ float tile[32][33];
    int bx = blockIdx.x*32, by = blockIdx.y*32;
    int tx = threadIdx.x, ty = threadIdx.y;
#pragma unroll
    for (int r = 0; r < 32; r += 8)
        tile[ty+r][tx] = src[(size_t)(by+ty+r)*DD + bx+tx];
    __syncthreads();
#pragma unroll
    for (int r = 0; r < 32; r += 8)
        dst[(size_t)(bx+ty+r)*DD + by+tx] = tile[tx][ty+r];
}

// vt[bh, d, s] = v[b, s, h*64+d]
__global__ void vtrans(const float* __restrict__ v, float* __restrict__ vt) {
    __shared__ float tile[32][33];
    int z = blockIdx.z, b = z >> 4, h = z & 15;
    int s0 = blockIdx.x*32, d0 = blockIdx.y*32;
    int tx = threadIdx.x, ty = threadIdx.y;
#pragma unroll
    for (int r = 0; r < 32; r += 8)
        tile[ty+r][tx] = v[(size_t)(b*SS + s0+ty+r)*DD + h*DH + d0 + tx];
    __syncthreads();
#pragma unroll
    for (int r = 0; r < 32; r += 8)
        vt[(size_t)z*DH*SS + (size_t)(d0+ty+r)*SS + s0+tx] = tile[tx][ty+r];
}

// ------------------------------ LayerNorm ----------------------------------
__global__ void ln_kernel(const float* __restrict__ x,
                          const float* __restrict__ g,
                          const float* __restrict__ b,
                          float* __restrict__ xn) {
    int row = blockIdx.x;
    const float* xr = x + (size_t)row * DD;
    float* outr = xn + (size_t)row * DD;
    int t = threadIdx.x;

    float s = 0.f, s2 = 0.f;
    for (int i = t; i < DD; i += 256) { float v = xr[i]; s += v; s2 += v*v; }

    __shared__ float rs[256], rs2[256];
    rs[t] = s; rs2[t] = s2; __syncthreads();
    for (int off = 128; off > 0; off >>= 1) {
        if (t < off) { rs[t] += rs[t+off]; rs2[t] += rs2[t+off]; }
        __syncthreads();
    }
    float mean = rs[0] * (1.0f/DD);
    float var  = rs2[0] * (1.0f/DD) - mean*mean;
    float inv  = rsqrtf(var + 1e-5f);
    for (int i = t; i < DD; i += 256)
        outr[i] = (xr[i] - mean) * inv * g[i] + b[i];
}

// ------------------------------ sinusoidal PE -------------------------------
__global__ void pe_kernel(float* __restrict__ pe) {
    int idx = blockIdx.x * blockDim.x + threadIdx.x;   // over S * D/2
    if (idx >= SS * (DD/2)) return;
    int s = idx / (DD/2);
    int i = idx % (DD/2);
    double div = exp(-(double)(2*i) * log(10000.0) / (double)DD);
    double ang = (double)s * div;
    pe[(size_t)s*DD + 2*i    ] = (float)sin(ang);
    pe[(size_t)s*DD + 2*i + 1] = (float)cos(ang);
}

// ------------- fused relative shift + softmax (in-place into scoreC) --------
__global__ void softmax_kernel(float* __restrict__ scoreC,
                               const float* __restrict__ scoreP) {
    int i  = blockIdx.x;
    int bh = blockIdx.y;
    size_t baseP = (size_t)bh * SS * SS;
    size_t baseC = baseP + (size_t)i * SS;
    int t = threadIdx.x;

    __shared__ float srow[SS];
    __shared__ float red[256];

    float m = -1e30f;
    for (int j = t; j < SS; j += 256) {
        float c = scoreC[baseC + j];
        float pv;
        if (j <= i)          pv = scoreP[baseP + (size_t)i*SS + (SS - 1 - i + j)];
        else if (j == i + 1) pv = 0.f;
        else                 pv = scoreP[baseP + (size_t)(i+1)*SS + (j - i - 2)];
        float sc = (c + pv) * SCALE;
        srow[j] = sc;
        m = fmaxf(m, sc);
    }
    red[t] = m; __syncthreads();
    for (int off = 128; off > 0; off >>= 1) {
        if (t < off) red[t] = fmaxf(red[t], red[t+off]);
        __syncthreads();
    }
    m = red[0];
    __syncthreads();

    float sum = 0.f;
    for (int j = t; j < SS; j += 256) {
        float e = expf(srow[j] - m);
        srow[j] = e;
        sum += e;
    }
    red[t] = sum; __syncthreads();
    for (int off = 128; off > 0; off >>= 1) {
        if (t < off) red[t] += red[t+off];
        __syncthreads();
    }
    float inv = 1.f / red[0];
    for (int j = t; j < SS; j += 256)
        scoreC[baseC + j] = srow[j] * inv;
}

// ------------------------------ launch -------------------------------------
extern "C" void kernel_launch(void* const* d_in, const int* in_sizes, int n_in,
                              void* d_out, int out_size) {
    const float* x    = (const float*)d_in[0];
    const float* ln_g = (const float*)d_in[1];
    const float* ln_b = (const float*)d_in[2];
    const float* Wq   = (const float*)d_in[3];
    const float* bq   = (const float*)d_in[4];
    const float* Wk   = (const float*)d_in[5];
    const float* bk   = (const float*)d_in[6];
    const float* Wv   = (const float*)d_in[7];
    const float* bv   = (const float*)d_in[8];
    const float* Wp   = (const float*)d_in[9];
    const float* Wo   = (const float*)d_in[10];
    const float* bo   = (const float*)d_in[11];
    const float* u_bias = (const float*)d_in[12];
    const float* v_bias = (const float*)d_in[13];
    float* out = (float*)d_out;

    float *xn, *q, *k, *v, *pe, *p, *head, *wt, *vt, *scoreC, *scoreP;
    cudaGetSymbolAddress((void**)&xn, g_xn);
    cudaGetSymbolAddress((void**)&q, g_q);
    cudaGetSymbolAddress((void**)&k, g_k);
    cudaGetSymbolAddress((void**)&v, g_v);
    cudaGetSymbolAddress((void**)&pe, g_pe);
    cudaGetSymbolAddress((void**)&p, g_p);
    cudaGetSymbolAddress((void**)&head, g_head);
    cudaGetSymbolAddress((void**)&wt, g_wt);
    cudaGetSymbolAddress((void**)&vt, g_vt);
    cudaGetSymbolAddress((void**)&scoreC, g_scoreC);
    cudaGetSymbolAddress((void**)&scoreP, g_scoreP);

    float* wtq = wt + 0*(size_t)DD*DD;
    float* wtk = wt + 1*(size_t)DD*DD;
    float* wtv = wt + 2*(size_t)DD*DD;
    float* wtp = wt + 3*(size_t)DD*DD;
    float* wto = wt + 4*(size_t)DD*DD;

    dim3 tb(32, 8);

    // 1. LayerNorm + PE + weight transposes
    ln_kernel<<<MM, 256>>>(x, ln_g, ln_b, xn);
    pe_kernel<<<(SS*(DD/2) + 255)/256, 256>>>(pe);
    transpose1024<<<dim3(32,32), tb>>>(Wq, wtq);
    transpose1024<<<dim3(32,32), tb>>>(Wk, wtk);
    transpose1024<<<dim3(32,32), tb>>>(Wv, wtv);
    transpose1024<<<dim3(32,32), tb>>>(Wp, wtp);
    transpose1024<<<dim3(32,32), tb>>>(Wo, wto);

    // 2. projections (tensor core, tf32)
    proj_tc<<<dim3(8, 32), 256>>>(xn, wtq, bq, q);
    proj_tc<<<dim3(8, 32), 256>>>(xn, wtk, bk, k);
    proj_tc<<<dim3(8, 32), 256>>>(xn, wtv, bv, v);
    proj_tc<<<dim3(8, 16), 256>>>(pe, wtp, nullptr, p);

    // 3. per-head V transpose
    vtrans<<<dim3(64, 2, BB*HH), tb>>>(v, vt);

    // 4. scores
    score_tc<<<dim3(16, 16, BB*HH), 256>>>(q, k, u_bias, scoreC, SS*DD);
    score_tc<<<dim3(16, 16, BB*HH), 256>>>(q, p, v_bias, scoreP, 0);

    // 5. relative shift + softmax (in-place)
    softmax_kernel<<<dim3(SS, BB*HH), 256>>>(scoreC, scoreP);

    // 6. attn @ V
    av_tc<<<dim3(8, 1, BB*HH), 256>>>(scoreC, vt, head);

    // 7. output projection
    proj_tc<<<dim3(8, 32), 256>>>(head, wto, bo, out);
}